// round 9
// baseline (speedup 1.0000x reference)
#include <cuda_runtime.h>
#include <cuda_fp16.h>
#include <stdint.h>

// ---- SOM constants (match reference) ----
#define NODES 4096
#define FEATS 256
#define BATCH 1024
#define SIGMA_F 70.4f        // max(M,N) * 1.1
#define TOTAL_ITER_F 100000.0f

typedef unsigned long long u64;

// ---- device scratch (no allocations allowed) ----
__device__ u64   g_best[BATCH];
__device__ float g_w2[NODES];
__device__ float g_s[NODES];          // column sums of lr_op
__device__ float g_params[3];         // [0]=lr, [1]=1/(2 r^2), [2]=r^2
__device__ __align__(16) __half g_xh[BATCH * FEATS];
__device__ __align__(16) __half g_xl[BATCH * FEATS];
__device__ __align__(16) __half g_wh[NODES * FEATS];
__device__ __align__(16) __half g_wl[NODES * FEATS];
__device__ __align__(16) __half g_xt[FEATS * BATCH];   // x transposed, fp16
__device__ __align__(16) __half g_L[NODES * BATCH];    // lr_op, n-major, fp16

// ---- PTX helpers ----
__device__ __forceinline__ uint32_t smem_u32(const void* p) {
    uint32_t a;
    asm("{ .reg .u64 t; cvta.to.shared.u64 t, %1; cvt.u32.u64 %0, t; }"
        : "=r"(a) : "l"(p));
    return a;
}
__device__ __forceinline__ void cp16(uint32_t dst, const void* src) {
    asm volatile("cp.async.cg.shared.global [%0], [%1], 16;"
                 :: "r"(dst), "l"(src));
}
#define CP_COMMIT() asm volatile("cp.async.commit_group;" ::: "memory")
#define CP_WAIT0()  asm volatile("cp.async.wait_group 0;" ::: "memory")

__device__ __forceinline__ void ldsm4(uint32_t* r, uint32_t addr) {
    asm volatile("ldmatrix.sync.aligned.m8n8.x4.shared.b16 {%0,%1,%2,%3}, [%4];"
                 : "=r"(r[0]), "=r"(r[1]), "=r"(r[2]), "=r"(r[3]) : "r"(addr));
}
__device__ __forceinline__ void mma16816(float* c, const uint32_t* a,
                                         const uint32_t* b) {
    asm volatile(
        "mma.sync.aligned.m16n8k16.row.col.f32.f16.f16.f32 "
        "{%0,%1,%2,%3}, {%4,%5,%6,%7}, {%8,%9}, {%0,%1,%2,%3};"
        : "+f"(c[0]), "+f"(c[1]), "+f"(c[2]), "+f"(c[3])
        : "r"(a[0]), "r"(a[1]), "r"(a[2]), "r"(a[3]), "r"(b[0]), "r"(b[1]));
}
__device__ __forceinline__ u64 packkey(float d, int n) {
    unsigned u = __float_as_uint(d);
    u = (u & 0x80000000u) ? ~u : (u | 0x80000000u);
    return ((u64)u << 32) | (unsigned)n;
}

// ============================================================
// K1: fused prep (grid-704, proven). Blocks [0,512): w split+w2;
// [512,640): x split; [640,704): x transpose (+ init in first 4).
// ============================================================
__device__ __forceinline__ void split8(const float* src, __half* hi, __half* lo,
                                       float* sumsq) {
    float4 va = ((const float4*)src)[0];
    float4 vb = ((const float4*)src)[1];
    float f[8] = {va.x, va.y, va.z, va.w, vb.x, vb.y, vb.z, vb.w};
    __half2 h2[4], l2[4];
    float s = 0.0f;
    #pragma unroll
    for (int i = 0; i < 4; i++) {
        float a = f[2 * i], b = f[2 * i + 1];
        s += a * a + b * b;
        float ha = __half2float(__float2half_rn(a));
        float hb = __half2float(__float2half_rn(b));
        h2[i] = __floats2half2_rn(ha, hb);
        l2[i] = __floats2half2_rn(a - ha, b - hb);
    }
    *(uint4*)hi = *(uint4*)h2;
    *(uint4*)lo = *(uint4*)l2;
    if (sumsq) *sumsq = s;
}

__global__ void __launch_bounds__(256) k_prep_all(const float* __restrict__ x,
                                                  const float* __restrict__ w,
                                                  const int* __restrict__ iter) {
    int bid = blockIdx.x;
    int t = threadIdx.x;
    int warp = t >> 5, lane = t & 31;

    if (bid < 512) {
        int n = bid * 8 + warp;
        int c = lane * 8;
        float s;
        split8(w + (size_t)n * FEATS + c, g_wh + n * FEATS + c,
               g_wl + n * FEATS + c, &s);
        #pragma unroll
        for (int o = 16; o; o >>= 1) s += __shfl_xor_sync(0xFFFFFFFFu, s, o);
        if (lane == 0) g_w2[n] = s;
    } else if (bid < 640) {
        int r = (bid - 512) * 8 + warp;
        int c = lane * 8;
        split8(x + (size_t)r * FEATS + c, g_xh + r * FEATS + c,
               g_xl + r * FEATS + c, nullptr);
    } else {
        __shared__ float s[64][65];
        int bx2 = bid - 640;
        if (bx2 < 4) {
            g_best[bx2 * 256 + t] = 0xFFFFFFFFFFFFFFFFull;
            if (bx2 == 0 && t == 0) {
                float lambda_g = TOTAL_ITER_F / SIGMA_F;
                float decay    = expf(-(float)iter[0] / lambda_g);
                float radius   = SIGMA_F * decay + 1e-6f;
                g_params[0] = 0.5f * decay;
                g_params[1] = 1.0f / (2.0f * radius * radius);
                g_params[2] = radius * radius;
            }
        }
        int b0 = (bx2 >> 2) * 64, d0 = (bx2 & 3) * 64;
        #pragma unroll
        for (int q = 0; q < 16; q++) {
            int e = q * 256 + t;
            int br = e >> 6, dc = e & 63;
            s[br][dc] = x[(size_t)(b0 + br) * FEATS + d0 + dc];
        }
        __syncthreads();
        #pragma unroll
        for (int q = 0; q < 16; q++) {
            int e = q * 256 + t;
            int dr = e >> 6, bc = e & 63;
            g_xt[(size_t)(d0 + dr) * BATCH + b0 + bc] = __float2half_rn(s[bc][dr]);
        }
    }
}

// ============================================================
// K2: BMU GEMM via HMMA (proven, unchanged). 256 thr, 128x128
// tile, grid 256 (2 CTAs/SM). 3-term split-fp16, 12 chunks.
// ============================================================
#define ASZ (128 * 144)
#define BSZ (128 * 144)
#define OFF_A 1024
#define OFF_B (1024 + 2 * ASZ)
#define SM_BMU (OFF_B + 2 * BSZ)

__device__ __forceinline__ void stage_bmu(uint32_t sb, int buf, int ch,
                                          int m0, int n0, int t) {
    int term = ch >> 2;
    int kk = (ch & 3) * 64;
    const __half* asrc = (term < 2) ? g_xh : g_xl;
    const __half* bsrc = (term == 1) ? g_wl : g_wh;
    uint32_t adst = sb + OFF_A + buf * ASZ;
    uint32_t bdst = sb + OFF_B + buf * BSZ;
    #pragma unroll
    for (int q = 0; q < 4; q++) {
        int g = t + 256 * q; int r = g >> 3, c = g & 7;
        cp16(adst + r * 144 + c * 16, asrc + (size_t)(m0 + r) * FEATS + kk + c * 8);
        cp16(bdst + r * 144 + c * 16, bsrc + (size_t)(n0 + r) * FEATS + kk + c * 8);
    }
    CP_COMMIT();
}

__global__ void __launch_bounds__(256, 2) k_bmu() {
    extern __shared__ char sm[];
    uint32_t sb = smem_u32(sm);
    float* w2s = (float*)sm;
    int t = threadIdx.x, lane = t & 31, warp = t >> 5;
    int wm = warp >> 1, wn = warp & 1;
    int n0 = blockIdx.x * 128;
    int m0 = blockIdx.y * 128;

    if (t < 128) w2s[t] = g_w2[n0 + t];

    float c[2][8][4];
    #pragma unroll
    for (int i = 0; i < 2; i++)
        #pragma unroll
        for (int j = 0; j < 8; j++)
            #pragma unroll
            for (int q = 0; q < 4; q++) c[i][j][q] = 0.0f;

    uint32_t aoff = (uint32_t)((lane & 15) * 144 + (lane >> 4) * 16);
    uint32_t boff = (uint32_t)(((lane & 7) + ((lane >> 4) << 3)) * 144
                               + (((lane >> 3) & 1) << 4));

    stage_bmu(sb, 0, 0, m0, n0, t);
    for (int ch = 0; ch < 12; ch++) {
        CP_WAIT0();
        __syncthreads();
        if (ch + 1 < 12) stage_bmu(sb, (ch + 1) & 1, ch + 1, m0, n0, t);

        uint32_t Ab = sb + OFF_A + (ch & 1) * ASZ + (wm * 32) * 144 + aoff;
        uint32_t Bb = sb + OFF_B + (ch & 1) * BSZ + (wn * 64) * 144 + boff;
        #pragma unroll
        for (int k16 = 0; k16 < 4; k16++) {
            uint32_t a[2][4], b[4][4];
            #pragma unroll
            for (int im = 0; im < 2; im++)
                ldsm4(a[im], Ab + im * 16 * 144 + k16 * 32);
            #pragma unroll
            for (int j2 = 0; j2 < 4; j2++)
                ldsm4(b[j2], Bb + j2 * 16 * 144 + k16 * 32);
            #pragma unroll
            for (int im = 0; im < 2; im++)
                #pragma unroll
                for (int j2 = 0; j2 < 4; j2++) {
                    mma16816(c[im][2 * j2],     a[im], b[j2]);
                    mma16816(c[im][2 * j2 + 1], a[im], b[j2] + 2);
                }
        }
    }

    #pragma unroll
    for (int im = 0; im < 2; im++) {
        #pragma unroll
        for (int h = 0; h < 2; h++) {
            float best = __int_as_float(0x7F800000);
            int bestn = 0;
            #pragma unroll
            for (int j8 = 0; j8 < 8; j8++) {
                int nl = wn * 64 + j8 * 8 + 2 * (lane & 3);
                float v0 = w2s[nl]     - 2.0f * c[im][j8][2 * h];
                float v1 = w2s[nl + 1] - 2.0f * c[im][j8][2 * h + 1];
                if (v0 < best) { best = v0; bestn = nl; }
                if (v1 < best) { best = v1; bestn = nl + 1; }
            }
            #pragma unroll
            for (int o = 1; o <= 2; o <<= 1) {
                float od = __shfl_xor_sync(0xFFFFFFFFu, best, o);
                int   on = __shfl_xor_sync(0xFFFFFFFFu, bestn, o);
                if (od < best || (od == best && on < bestn)) { best = od; bestn = on; }
            }
            if ((lane & 3) == 0) {
                int m = m0 + wm * 32 + im * 16 + h * 8 + (lane >> 2);
                atomicMin(&g_best[m], packkey(best, n0 + bestn));
            }
        }
    }
}

// ============================================================
// K3: lr_op generation, separable-exp table. CTA = 16 n-rows x
// full batch; grid 256. L[n][b] fp16 + row sums S[n].
// ============================================================
__global__ void __launch_bounds__(256) k_lgen() {
    __shared__ uint8_t s_bi[BATCH];
    __shared__ uint8_t s_bj[BATCH];
    __shared__ float tabA[64], tabB[64];
    int t = threadIdx.x;
    int n0 = blockIdx.x * 16;
    float lr = g_params[0], inv2r2 = g_params[1], r2 = g_params[2];

    if (t < 64) {
        float e = __expf(-(float)(t * t) * inv2r2);
        tabA[t] = lr * e;
        tabB[t] = e;
    }
    #pragma unroll
    for (int q = 0; q < 4; q++) {
        int b = t + 256 * q;
        int bmu = (int)(unsigned)(g_best[b] & 0xFFFFFFFFull);
        s_bi[b] = (uint8_t)(bmu >> 6);
        s_bj[b] = (uint8_t)(bmu & 63);
    }
    __syncthreads();

    int nr = t >> 4, bc = t & 15;
    int n = n0 + nr;
    int ni = n >> 6, nj = n & 63;
    float sum = 0.0f;

    #pragma unroll
    for (int j = 0; j < 8; j++) {
        __half2 hv[4];
        #pragma unroll
        for (int e = 0; e < 4; e++) {
            int b0 = bc * 64 + j * 8 + 2 * e;
            int di0 = ni - (int)s_bi[b0], dj0 = nj - (int)s_bj[b0];
            int d20 = di0 * di0 + dj0 * dj0;
            float v0 = ((float)d20 <= r2) ? tabA[abs(di0)] * tabB[abs(dj0)] : 0.0f;
            int di1 = ni - (int)s_bi[b0 + 1], dj1 = nj - (int)s_bj[b0 + 1];
            int d21 = di1 * di1 + dj1 * dj1;
            float v1 = ((float)d21 <= r2) ? tabA[abs(di1)] * tabB[abs(dj1)] : 0.0f;
            sum += v0 + v1;
            hv[e] = __floats2half2_rn(v0, v1);
        }
        *(uint4*)&g_L[(size_t)n * BATCH + bc * 64 + j * 8] = *(uint4*)hv;
    }

    // reduce sum across the 16 threads of this row (xor of bits 0-3)
    #pragma unroll
    for (int o = 8; o; o >>= 1) sum += __shfl_xor_sync(0xFFFFFFFFu, sum, o);
    if (bc == 0) g_s[n] = sum;
}

// ============================================================
// K4: update GEMM, PURE HMMA. C[n,d] = sum_b L[n,b]*Xt[d,b].
// CTA tile 64n x 128d, grid 128, 256 thr, warps 2n x 4d
// (warp tile 32x32, ldsm:mma = 1:2). cp.async double-buffered.
// ============================================================
#define UASZ (64 * 144)
#define UBSZ (128 * 144)

__global__ void __launch_bounds__(256, 2) k_update(const float* __restrict__ w,
                                                   float* __restrict__ out,
                                                   int out_size) {
    __shared__ __align__(16) __half As[2][64 * 72];
    __shared__ __align__(16) __half Bs[2][128 * 72];
    uint32_t sbA = smem_u32(As);
    uint32_t sbB = smem_u32(Bs);

    int t = threadIdx.x, lane = t & 31, warp = t >> 5;
    int wn = warp >> 2, wd = warp & 3;     // 2n x 4d warp grid
    int bx = blockIdx.x;
    int n0 = (bx >> 1) * 64;
    int d0 = (bx & 1) * 128;

    float c[2][4][4];
    #pragma unroll
    for (int i = 0; i < 2; i++)
        #pragma unroll
        for (int j = 0; j < 4; j++)
            #pragma unroll
            for (int q = 0; q < 4; q++) c[i][j][q] = 0.0f;

    uint32_t aoff = (uint32_t)((lane & 15) * 144 + (lane >> 4) * 16);
    uint32_t boff = (uint32_t)(((lane & 7) + ((lane >> 4) << 3)) * 144
                               + (((lane >> 3) & 1) << 4));

    auto stage = [&](int buf, int ch) {
        uint32_t adst = sbA + buf * UASZ;
        #pragma unroll
        for (int q = 0; q < 2; q++) {
            int g = t + 256 * q; int r = g >> 3, cc = g & 7;
            cp16(adst + r * 144 + cc * 16,
                 g_L + (size_t)(n0 + r) * BATCH + ch * 64 + cc * 8);
        }
        uint32_t bdst = sbB + buf * UBSZ;
        #pragma unroll
        for (int q = 0; q < 4; q++) {
            int g = t + 256 * q; int r = g >> 3, cc = g & 7;
            cp16(bdst + r * 144 + cc * 16,
                 g_xt + (size_t)(d0 + r) * BATCH + ch * 64 + cc * 8);
        }
        CP_COMMIT();
    };

    stage(0, 0);
    for (int ch = 0; ch < 16; ch++) {
        CP_WAIT0();
        __syncthreads();
        if (ch + 1 < 16) stage((ch + 1) & 1, ch + 1);

        uint32_t Ab = sbA + (ch & 1) * UASZ + (wn * 32) * 144 + aoff;
        uint32_t Bb = sbB + (ch & 1) * UBSZ + (wd * 32) * 144 + boff;
        #pragma unroll
        for (int k16 = 0; k16 < 4; k16++) {
            uint32_t a[2][4], b[2][4];
            #pragma unroll
            for (int im = 0; im < 2; im++)
                ldsm4(a[im], Ab + im * 16 * 144 + k16 * 32);
            #pragma unroll
            for (int j2 = 0; j2 < 2; j2++)
                ldsm4(b[j2], Bb + j2 * 16 * 144 + k16 * 32);
            #pragma unroll
            for (int im = 0; im < 2; im++)
                #pragma unroll
                for (int jd = 0; jd < 4; jd++)
                    mma16816(c[im][jd], a[im], b[jd >> 1] + (jd & 1) * 2);
        }
    }

    const float invB = 1.0f / (float)BATCH;
    #pragma unroll
    for (int im = 0; im < 2; im++) {
        #pragma unroll
        for (int h = 0; h < 2; h++) {
            int nl = wn * 32 + im * 16 + h * 8 + (lane >> 2);
            int n = n0 + nl;
            float s = g_s[n];
            #pragma unroll
            for (int jd = 0; jd < 4; jd++) {
                int d = d0 + wd * 32 + jd * 8 + 2 * (lane & 3);
                size_t idx = (size_t)n * FEATS + d;
                float2 wv = *(const float2*)&w[idx];
                float a0 = c[im][jd][2 * h], a1 = c[im][jd][2 * h + 1];
                float2 o;
                o.x = wv.x + (a0 - s * wv.x) * invB;
                o.y = wv.y + (a1 - s * wv.y) * invB;
                *(float2*)&out[idx] = o;
            }
        }
    }

    // emit bmu indices (as float) after the map if there is room
    if (bx < 4 && out_size >= NODES * FEATS + BATCH) {
        int b = bx * 256 + t;
        out[NODES * FEATS + b] =
            (float)(unsigned)(g_best[b] & 0xFFFFFFFFull);
    }
}

// ============================================================
extern "C" void kernel_launch(void* const* d_in, const int* in_sizes, int n_in,
                              void* d_out, int out_size) {
    const float* x = nullptr;
    const float* w = nullptr;
    const int* iter = nullptr;
    for (int i = 0; i < n_in; i++) {
        if (in_sizes[i] == BATCH * FEATS)      x = (const float*)d_in[i];
        else if (in_sizes[i] == NODES * FEATS) w = (const float*)d_in[i];
        else if (in_sizes[i] == 1)             iter = (const int*)d_in[i];
    }
    float* out = (float*)d_out;

    cudaFuncSetAttribute(k_bmu, cudaFuncAttributeMaxDynamicSharedMemorySize, SM_BMU);

    k_prep_all<<<704, 256>>>(x, w, iter);
    dim3 gb(NODES / 128, BATCH / 128);
    k_bmu<<<gb, 256, SM_BMU>>>();
    k_lgen<<<NODES / 16, 256>>>();
    k_update<<<(NODES / 64) * (FEATS / 128), 256>>>(w, out, out_size);
}

// round 10
// speedup vs baseline: 1.0810x; 1.0810x over previous
#include <cuda_runtime.h>
#include <cuda_fp16.h>
#include <stdint.h>

// ---- SOM constants (match reference) ----
#define NODES 4096
#define FEATS 256
#define BATCH 1024
#define SIGMA_F 70.4f        // max(M,N) * 1.1
#define TOTAL_ITER_F 100000.0f

typedef unsigned long long u64;

// ---- device scratch (no allocations allowed) ----
__device__ u64   g_best[BATCH];
__device__ float g_w2[NODES];
__device__ float g_params[3];         // [0]=lr, [1]=1/(2 r^2), [2]=r^2
__device__ __align__(16) __half g_xh[BATCH * FEATS];
__device__ __align__(16) __half g_xl[BATCH * FEATS];
__device__ __align__(16) __half g_wh[NODES * FEATS];
__device__ __align__(16) __half g_wl[NODES * FEATS];
__device__ __align__(16) __half g_xt[FEATS * BATCH];   // x transposed, fp16

// ---- PTX helpers ----
__device__ __forceinline__ uint32_t smem_u32(const void* p) {
    uint32_t a;
    asm("{ .reg .u64 t; cvta.to.shared.u64 t, %1; cvt.u32.u64 %0, t; }"
        : "=r"(a) : "l"(p));
    return a;
}
__device__ __forceinline__ void cp16(uint32_t dst, const void* src) {
    asm volatile("cp.async.cg.shared.global [%0], [%1], 16;"
                 :: "r"(dst), "l"(src));
}
#define CP_COMMIT() asm volatile("cp.async.commit_group;" ::: "memory")
#define CP_WAIT0()  asm volatile("cp.async.wait_group 0;" ::: "memory")
#define CP_WAIT1()  asm volatile("cp.async.wait_group 1;" ::: "memory")

__device__ __forceinline__ void ldsm4(uint32_t* r, uint32_t addr) {
    asm volatile("ldmatrix.sync.aligned.m8n8.x4.shared.b16 {%0,%1,%2,%3}, [%4];"
                 : "=r"(r[0]), "=r"(r[1]), "=r"(r[2]), "=r"(r[3]) : "r"(addr));
}
__device__ __forceinline__ void mma16816(float* c, const uint32_t* a,
                                         const uint32_t* b) {
    asm volatile(
        "mma.sync.aligned.m16n8k16.row.col.f32.f16.f16.f32 "
        "{%0,%1,%2,%3}, {%4,%5,%6,%7}, {%8,%9}, {%0,%1,%2,%3};"
        : "+f"(c[0]), "+f"(c[1]), "+f"(c[2]), "+f"(c[3])
        : "r"(a[0]), "r"(a[1]), "r"(a[2]), "r"(a[3]), "r"(b[0]), "r"(b[1]));
}
__device__ __forceinline__ u64 packkey(float d, int n) {
    unsigned u = __float_as_uint(d);
    u = (u & 0x80000000u) ? ~u : (u | 0x80000000u);
    return ((u64)u << 32) | (unsigned)n;
}

// ============================================================
// K1: fused prep (grid-704, proven 6.3us).
// ============================================================
__device__ __forceinline__ void split8(const float* src, __half* hi, __half* lo,
                                       float* sumsq) {
    float4 va = ((const float4*)src)[0];
    float4 vb = ((const float4*)src)[1];
    float f[8] = {va.x, va.y, va.z, va.w, vb.x, vb.y, vb.z, vb.w};
    __half2 h2[4], l2[4];
    float s = 0.0f;
    #pragma unroll
    for (int i = 0; i < 4; i++) {
        float a = f[2 * i], b = f[2 * i + 1];
        s += a * a + b * b;
        float ha = __half2float(__float2half_rn(a));
        float hb = __half2float(__float2half_rn(b));
        h2[i] = __floats2half2_rn(ha, hb);
        l2[i] = __floats2half2_rn(a - ha, b - hb);
    }
    *(uint4*)hi = *(uint4*)h2;
    *(uint4*)lo = *(uint4*)l2;
    if (sumsq) *sumsq = s;
}

__global__ void __launch_bounds__(256) k_prep_all(const float* __restrict__ x,
                                                  const float* __restrict__ w,
                                                  const int* __restrict__ iter) {
    int bid = blockIdx.x;
    int t = threadIdx.x;
    int warp = t >> 5, lane = t & 31;

    if (bid < 512) {
        int n = bid * 8 + warp;
        int c = lane * 8;
        float s;
        split8(w + (size_t)n * FEATS + c, g_wh + n * FEATS + c,
               g_wl + n * FEATS + c, &s);
        #pragma unroll
        for (int o = 16; o; o >>= 1) s += __shfl_xor_sync(0xFFFFFFFFu, s, o);
        if (lane == 0) g_w2[n] = s;
    } else if (bid < 640) {
        int r = (bid - 512) * 8 + warp;
        int c = lane * 8;
        split8(x + (size_t)r * FEATS + c, g_xh + r * FEATS + c,
               g_xl + r * FEATS + c, nullptr);
    } else {
        __shared__ float s[64][65];
        int bx2 = bid - 640;
        if (bx2 < 4) {
            g_best[bx2 * 256 + t] = 0xFFFFFFFFFFFFFFFFull;
            if (bx2 == 0 && t == 0) {
                float lambda_g = TOTAL_ITER_F / SIGMA_F;
                float decay    = expf(-(float)iter[0] / lambda_g);
                float radius   = SIGMA_F * decay + 1e-6f;
                g_params[0] = 0.5f * decay;
                g_params[1] = 1.0f / (2.0f * radius * radius);
                g_params[2] = radius * radius;
            }
        }
        int b0 = (bx2 >> 2) * 64, d0 = (bx2 & 3) * 64;
        #pragma unroll
        for (int q = 0; q < 16; q++) {
            int e = q * 256 + t;
            int br = e >> 6, dc = e & 63;
            s[br][dc] = x[(size_t)(b0 + br) * FEATS + d0 + dc];
        }
        __syncthreads();
        #pragma unroll
        for (int q = 0; q < 16; q++) {
            int e = q * 256 + t;
            int dr = e >> 6, bc = e & 63;
            g_xt[(size_t)(d0 + dr) * BATCH + b0 + bc] = __float2half_rn(s[bc][dr]);
        }
    }
}

// ============================================================
// K2: BMU GEMM via HMMA (proven, unchanged).
// ============================================================
#define ASZ (128 * 144)
#define BSZ (128 * 144)
#define OFF_A 1024
#define OFF_B (1024 + 2 * ASZ)
#define SM_BMU (OFF_B + 2 * BSZ)

__device__ __forceinline__ void stage_bmu(uint32_t sb, int buf, int ch,
                                          int m0, int n0, int t) {
    int term = ch >> 2;
    int kk = (ch & 3) * 64;
    const __half* asrc = (term < 2) ? g_xh : g_xl;
    const __half* bsrc = (term == 1) ? g_wl : g_wh;
    uint32_t adst = sb + OFF_A + buf * ASZ;
    uint32_t bdst = sb + OFF_B + buf * BSZ;
    #pragma unroll
    for (int q = 0; q < 4; q++) {
        int g = t + 256 * q; int r = g >> 3, c = g & 7;
        cp16(adst + r * 144 + c * 16, asrc + (size_t)(m0 + r) * FEATS + kk + c * 8);
        cp16(bdst + r * 144 + c * 16, bsrc + (size_t)(n0 + r) * FEATS + kk + c * 8);
    }
    CP_COMMIT();
}

__global__ void __launch_bounds__(256, 2) k_bmu() {
    extern __shared__ char sm[];
    uint32_t sb = smem_u32(sm);
    float* w2s = (float*)sm;
    int t = threadIdx.x, lane = t & 31, warp = t >> 5;
    int wm = warp >> 1, wn = warp & 1;
    int n0 = blockIdx.x * 128;
    int m0 = blockIdx.y * 128;

    if (t < 128) w2s[t] = g_w2[n0 + t];

    float c[2][8][4];
    #pragma unroll
    for (int i = 0; i < 2; i++)
        #pragma unroll
        for (int j = 0; j < 8; j++)
            #pragma unroll
            for (int q = 0; q < 4; q++) c[i][j][q] = 0.0f;

    uint32_t aoff = (uint32_t)((lane & 15) * 144 + (lane >> 4) * 16);
    uint32_t boff = (uint32_t)(((lane & 7) + ((lane >> 4) << 3)) * 144
                               + (((lane >> 3) & 1) << 4));

    stage_bmu(sb, 0, 0, m0, n0, t);
    for (int ch = 0; ch < 12; ch++) {
        CP_WAIT0();
        __syncthreads();
        if (ch + 1 < 12) stage_bmu(sb, (ch + 1) & 1, ch + 1, m0, n0, t);

        uint32_t Ab = sb + OFF_A + (ch & 1) * ASZ + (wm * 32) * 144 + aoff;
        uint32_t Bb = sb + OFF_B + (ch & 1) * BSZ + (wn * 64) * 144 + boff;
        #pragma unroll
        for (int k16 = 0; k16 < 4; k16++) {
            uint32_t a[2][4], b[4][4];
            #pragma unroll
            for (int im = 0; im < 2; im++)
                ldsm4(a[im], Ab + im * 16 * 144 + k16 * 32);
            #pragma unroll
            for (int j2 = 0; j2 < 4; j2++)
                ldsm4(b[j2], Bb + j2 * 16 * 144 + k16 * 32);
            #pragma unroll
            for (int im = 0; im < 2; im++)
                #pragma unroll
                for (int j2 = 0; j2 < 4; j2++) {
                    mma16816(c[im][2 * j2],     a[im], b[j2]);
                    mma16816(c[im][2 * j2 + 1], a[im], b[j2] + 2);
                }
        }
    }

    #pragma unroll
    for (int im = 0; im < 2; im++) {
        #pragma unroll
        for (int h = 0; h < 2; h++) {
            float best = __int_as_float(0x7F800000);
            int bestn = 0;
            #pragma unroll
            for (int j8 = 0; j8 < 8; j8++) {
                int nl = wn * 64 + j8 * 8 + 2 * (lane & 3);
                float v0 = w2s[nl]     - 2.0f * c[im][j8][2 * h];
                float v1 = w2s[nl + 1] - 2.0f * c[im][j8][2 * h + 1];
                if (v0 < best) { best = v0; bestn = nl; }
                if (v1 < best) { best = v1; bestn = nl + 1; }
            }
            #pragma unroll
            for (int o = 1; o <= 2; o <<= 1) {
                float od = __shfl_xor_sync(0xFFFFFFFFu, best, o);
                int   on = __shfl_xor_sync(0xFFFFFFFFu, bestn, o);
                if (od < best || (od == best && on < bestn)) { best = od; bestn = on; }
            }
            if ((lane & 3) == 0) {
                int m = m0 + wm * 32 + im * 16 + h * 8 + (lane >> 2);
                atomicMin(&g_best[m], packkey(best, n0 + bestn));
            }
        }
    }
}

// ============================================================
// K3: update GEMM. C[n,d] = sum_b L[n,b]*Xt[d,b]. CTA 64n x 128d,
// grid 128, 256 thr, warps 2n x 4d (32x32 warp tile).
// X: 3-stage cp.async pipeline (wait_group 1). L: generated inline
// per chunk from separable exp tables (2 LDS + FMUL per element),
// double-buffered in smem. S[n] accumulated alongside.
// ============================================================
#define ULSZ (64 * 144)              // one L stage: 64n x 72 halves
#define UXSZ (128 * 144)             // one X stage: 128d x 72 halves
#define UOFF_L 0
#define UOFF_X (2 * ULSZ)
#define UOFF_TA (UOFF_X + 3 * UXSZ)          // tabA: 64 floats
#define UOFF_TB (UOFF_TA + 256)              // tabB: 64 floats
#define UOFF_BI (UOFF_TB + 256)              // s_bi: 1024 bytes
#define UOFF_BJ (UOFF_BI + 1024)             // s_bj: 1024 bytes
#define UOFF_SP (UOFF_BJ + 1024)             // s_part: 256 floats
#define SM_UPD  (UOFF_SP + 1024 + 256)

__global__ void __launch_bounds__(256) k_update(const float* __restrict__ w,
                                                float* __restrict__ out,
                                                int out_size) {
    extern __shared__ char sm[];
    uint32_t sb = smem_u32(sm);
    __half* Ls   = (__half*)(sm + UOFF_L);
    float*  tabA = (float*)(sm + UOFF_TA);
    float*  tabB = (float*)(sm + UOFF_TB);
    uint8_t* sbi = (uint8_t*)(sm + UOFF_BI);
    uint8_t* sbj = (uint8_t*)(sm + UOFF_BJ);
    float*  s_part = (float*)(sm + UOFF_SP);

    int t = threadIdx.x, lane = t & 31, warp = t >> 5;
    int wn = warp >> 2, wd = warp & 3;     // 2n x 4d warp grid
    int bx = blockIdx.x;
    int n0 = (bx >> 1) * 64;
    int d0 = (bx & 1) * 128;

    float lr = g_params[0], inv2r2 = g_params[1], r2 = g_params[2];

    // prologue: tables + bmu coords
    if (t < 64) {
        float e = __expf(-(float)(t * t) * inv2r2);
        tabA[t] = lr * e;
        tabB[t] = e;
    }
    #pragma unroll
    for (int q = 0; q < 4; q++) {
        int b = t + 256 * q;
        int bmu = (int)(unsigned)(g_best[b] & 0xFFFFFFFFull);
        sbi[b] = (uint8_t)(bmu >> 6);
        sbj[b] = (uint8_t)(bmu & 63);
    }

    // L generation thread mapping: row n_l = t>>2, b-quarter = t&3
    int n_l = t >> 2;
    int bq = (t & 3) * 16;
    int gn = n0 + n_l;
    int ni = gn >> 6, nj = gn & 63;
    float s_local = 0.0f;

    auto gen_L = [&](int ch, int buf) {
        __half* Lrow = Ls + buf * (ULSZ / 2) + n_l * 72;
        int bc0 = ch * 64;
        #pragma unroll
        for (int j = 0; j < 8; j++) {
            int b0 = bc0 + bq + 2 * j;
            int di0 = ni - (int)sbi[b0],     dj0 = nj - (int)sbj[b0];
            int di1 = ni - (int)sbi[b0 + 1], dj1 = nj - (int)sbj[b0 + 1];
            float d20 = (float)(di0 * di0 + dj0 * dj0);
            float d21 = (float)(di1 * di1 + dj1 * dj1);
            float v0 = (d20 <= r2) ? tabA[abs(di0)] * tabB[abs(dj0)] : 0.0f;
            float v1 = (d21 <= r2) ? tabA[abs(di1)] * tabB[abs(dj1)] : 0.0f;
            s_local += v0 + v1;
            *(__half2*)(Lrow + bq + 2 * j) = __floats2half2_rn(v0, v1);
        }
    };

    auto stage_x = [&](int ch) {
        uint32_t xdst = sb + UOFF_X + (ch % 3) * UXSZ;
        #pragma unroll
        for (int q = 0; q < 4; q++) {
            int g = t + 256 * q; int r = g >> 3, cc = g & 7;
            cp16(xdst + r * 144 + cc * 16,
                 g_xt + (size_t)(d0 + r) * BATCH + ch * 64 + cc * 8);
        }
        CP_COMMIT();
    };

    float c[2][4][4];
    #pragma unroll
    for (int i = 0; i < 2; i++)
        #pragma unroll
        for (int j = 0; j < 4; j++)
            #pragma unroll
            for (int q = 0; q < 4; q++) c[i][j][q] = 0.0f;

    uint32_t aoff = (uint32_t)((lane & 15) * 144 + (lane >> 4) * 16);
    uint32_t boff = (uint32_t)(((lane & 7) + ((lane >> 4) << 3)) * 144
                               + (((lane >> 3) & 1) << 4));

    stage_x(0);
    stage_x(1);
    __syncthreads();       // tables + sbi/sbj visible before first gen_L use

    for (int ch = 0; ch < 16; ch++) {
        CP_WAIT1();        // X(ch) complete (<=1 group outstanding)
        gen_L(ch, ch & 1); // write L(ch); prior reads of this buf ended @ sync(ch-1)
        __syncthreads();   // X(ch) + L(ch) visible to all warps
        if (ch + 2 < 16) stage_x(ch + 2);

        uint32_t Ab = sb + UOFF_L + (ch & 1) * ULSZ + (wn * 32) * 144 + aoff;
        uint32_t Bb = sb + UOFF_X + (ch % 3) * UXSZ + (wd * 32) * 144 + boff;
        #pragma unroll
        for (int k16 = 0; k16 < 4; k16++) {
            uint32_t a[2][4], b[2][4];
            #pragma unroll
            for (int im = 0; im < 2; im++)
                ldsm4(a[im], Ab + im * 16 * 144 + k16 * 32);
            #pragma unroll
            for (int j2 = 0; j2 < 2; j2++)
                ldsm4(b[j2], Bb + j2 * 16 * 144 + k16 * 32);
            #pragma unroll
            for (int im = 0; im < 2; im++)
                #pragma unroll
                for (int jd = 0; jd < 4; jd++)
                    mma16816(c[im][jd], a[im], b[jd >> 1] + (jd & 1) * 2);
        }
    }

    // S[n]: reduce the 4 per-row partials
    s_part[t] = s_local;
    __syncthreads();
    float* s_sm = tabA;    // reuse (tables no longer needed)
    if (t < 64)
        s_sm[t] = s_part[t * 4] + s_part[t * 4 + 1]
                + s_part[t * 4 + 2] + s_part[t * 4 + 3];
    __syncthreads();

    const float invB = 1.0f / (float)BATCH;
    #pragma unroll
    for (int im = 0; im < 2; im++) {
        #pragma unroll
        for (int h = 0; h < 2; h++) {
            int nl = wn * 32 + im * 16 + h * 8 + (lane >> 2);
            int n = n0 + nl;
            float s = s_sm[nl];
            #pragma unroll
            for (int jd = 0; jd < 4; jd++) {
                int d = d0 + wd * 32 + jd * 8 + 2 * (lane & 3);
                size_t idx = (size_t)n * FEATS + d;
                float2 wv = *(const float2*)&w[idx];
                float a0 = c[im][jd][2 * h], a1 = c[im][jd][2 * h + 1];
                float2 o;
                o.x = wv.x + (a0 - s * wv.x) * invB;
                o.y = wv.y + (a1 - s * wv.y) * invB;
                *(float2*)&out[idx] = o;
            }
        }
    }

    // emit bmu indices (as float) after the map if there is room
    if (bx < 4 && out_size >= NODES * FEATS + BATCH) {
        int b = bx * 256 + t;
        out[NODES * FEATS + b] =
            (float)(unsigned)(g_best[b] & 0xFFFFFFFFull);
    }
}

// ============================================================
extern "C" void kernel_launch(void* const* d_in, const int* in_sizes, int n_in,
                              void* d_out, int out_size) {
    const float* x = nullptr;
    const float* w = nullptr;
    const int* iter = nullptr;
    for (int i = 0; i < n_in; i++) {
        if (in_sizes[i] == BATCH * FEATS)      x = (const float*)d_in[i];
        else if (in_sizes[i] == NODES * FEATS) w = (const float*)d_in[i];
        else if (in_sizes[i] == 1)             iter = (const int*)d_in[i];
    }
    float* out = (float*)d_out;

    cudaFuncSetAttribute(k_bmu, cudaFuncAttributeMaxDynamicSharedMemorySize, SM_BMU);
    cudaFuncSetAttribute(k_update, cudaFuncAttributeMaxDynamicSharedMemorySize, SM_UPD);

    k_prep_all<<<704, 256>>>(x, w, iter);
    dim3 gb(NODES / 128, BATCH / 128);
    k_bmu<<<gb, 256, SM_BMU>>>();
    k_update<<<(NODES / 64) * (FEATS / 128), 256, SM_UPD>>>(w, out, out_size);
}